// round 16
// baseline (speedup 1.0000x reference)
#include <cuda_runtime.h>
#include <cuda_bf16.h>
#include <cstdint>

#define W 512
#define H 512
#define IMGS 128
#define STRIPB 64                      // rows per CTA
#define STRIPS (H / STRIPB)            // 8
#define BLOCK 128
#define WPB 4
#define GRID (IMGS * STRIPS)           // 1024
#define CPT 8
#define NELEM 33554432.0f
#define FULLM 0xffffffffu

#define CHROWS 2
#define CHB (CHROWS * W * 4)           // 4096
#define RINGN 4
#define PIPEB (RINGN * CHB)            // 16384
#define NCHUNK 17                      // chunks per pipe (34 rows)

__device__ float g_partials[GRID];
__device__ unsigned int g_count;

__device__ __forceinline__ void mbar_init(unsigned bar, unsigned cnt) {
    asm volatile("mbarrier.init.shared.b64 [%0], %1;" :: "r"(bar), "r"(cnt) : "memory");
}
__device__ __forceinline__ void mbar_wait(unsigned bar, unsigned parity) {
    asm volatile(
        "{\n\t.reg .pred P;\n\t"
        "WL_%=:\n\t"
        "mbarrier.try_wait.parity.acquire.cta.shared::cta.b64 P, [%0], %1, 0x989680;\n\t"
        "@P bra.uni WD_%=;\n\t"
        "bra.uni WL_%=;\n\t"
        "WD_%=:\n\t}"
        :: "r"(bar), "r"(parity) : "memory");
}
__device__ __forceinline__ void mbar_arrive(unsigned bar) {
    asm volatile("mbarrier.arrive.shared.b64 _, [%0];" :: "r"(bar) : "memory");
}
__device__ __forceinline__ void mbar_expect(unsigned bar, unsigned bytes) {
    asm volatile("mbarrier.arrive.expect_tx.shared.b64 _, [%0], %1;"
                 :: "r"(bar), "r"(bytes) : "memory");
}
__device__ __forceinline__ void bulk_cp(unsigned dst, const float* src, unsigned bytes,
                                        unsigned bar) {
    asm volatile("cp.async.bulk.shared::cta.global.mbarrier::complete_tx::bytes "
                 "[%0], [%1], %2, [%3];"
                 :: "r"(dst), "l"(src), "r"(bytes), "r"(bar) : "memory");
}

struct Carry {
    float xp[CPT];
    float erp[CPT];
    float xLp, xRp;
    float erpR;
};

__device__ __forceinline__ void step_compute(const float xc[CPT], float xLc, float xRc,
                                             int lane, bool rightEdge,
                                             Carry& C, float& acc) {
    float vm[CPT];
#pragma unroll
    for (int i = 0; i < CPT; i++) vm[i] = fminf(C.xp[i], xc[i]);
    float vmL = fminf(C.xLp, xLc);
    float vmR = fminf(C.xRp, xRc);

    float left = __shfl_up_sync(FULLM, vm[CPT-1], 1);
    if (lane == 0) left = vmL;
    float ern[CPT];
    ern[0] = fminf(left, vm[0]);
#pragma unroll
    for (int i = 1; i < CPT; i++) ern[i] = fminf(vm[i-1], vm[i]);
    float ernR = fminf(vm[CPT-1], vmR);

    float h[CPT];
#pragma unroll
    for (int i = 0; i < CPT; i++) h[i] = fmaxf(C.erp[i], ern[i]);
    float hR = fmaxf(C.erpR, ernR);

    float hn = __shfl_down_sync(FULLM, h[0], 1);
    if (lane == 31) hn = rightEdge ? h[CPT-1] : hR;
#pragma unroll
    for (int i = 0; i < CPT-1; i++) {
        float di = fmaxf(h[i], h[i+1]);
        float d = C.xp[i] - di;
        acc = fmaf(d, d, acc);
    }
    {
        float di = fmaxf(h[CPT-1], hn);
        float d = C.xp[CPT-1] - di;
        acc = fmaf(d, d, acc);
    }

#pragma unroll
    for (int i = 0; i < CPT; i++) { C.xp[i] = xc[i]; C.erp[i] = ern[i]; }
    C.xLp = xLc; C.xRp = xRc; C.erpR = ernR;
}

__device__ __forceinline__ void final_emit(int lane, bool rightEdge, Carry& C, float& acc) {
    float hn = __shfl_down_sync(FULLM, C.erp[0], 1);
    if (lane == 31) hn = rightEdge ? C.erp[CPT-1] : C.erpR;
#pragma unroll
    for (int i = 0; i < CPT-1; i++) {
        float di = fmaxf(C.erp[i], C.erp[i+1]);
        float d = C.xp[i] - di;
        acc = fmaf(d, d, acc);
    }
    float di = fmaxf(C.erp[CPT-1], hn);
    float d = C.xp[CPT-1] - di;
    acc = fmaf(d, d, acc);
}

__global__ void __launch_bounds__(BLOCK, 7)
opening_loss_kernel(const float* __restrict__ labels, float* __restrict__ out) {
    __shared__ __align__(16) char sdata[2 * PIPEB];            // 32768 B
    __shared__ __align__(8) unsigned long long mbars[16];

    const int lane = threadIdx.x & 31;
    const int wid  = threadIdx.x >> 5;
    const int pipe = wid >> 1;
    const int cw   = wid & 1;

    const int img   = blockIdx.x >> 3;
    const int strip = blockIdx.x & (STRIPS - 1);
    const int r0 = strip * STRIPB;
    const float* base = labels + (size_t)img * (W * H);

    const unsigned mb0 = (unsigned)__cvta_generic_to_shared(mbars);
    // layout: pipe p: full[s] at (p*8+s), empty[s] at (p*8+4+s)
    if (threadIdx.x == 0) {
#pragma unroll
        for (int p = 0; p < 2; p++) {
#pragma unroll
            for (int s = 0; s < RINGN; s++) {
                mbar_init(mb0 + (p*8+s)*8u, 1u);     // full
                mbar_init(mb0 + (p*8+4+s)*8u, 2u);   // empty (both consumer warps)
            }
        }
    }
    __syncthreads();

    const bool p1 = (pipe == 1);
    const bool lastStrip = (r0 + STRIPB == H);
    const bool dupInit = (!p1 && strip == 0);   // top edge: x[-1]=x[0]
    const bool p1Last  = (p1 && lastStrip);

    const int rA = p1 ? (r0 + 31) : ((r0 > 0) ? r0 - 1 : 0);
    const unsigned psm = (unsigned)__cvta_generic_to_shared(sdata) + pipe * PIPEB;
    const unsigned fullb  = mb0 + (unsigned)(pipe*8)     * 8u;   // + stage*8
    const unsigned emptyb = mb0 + (unsigned)(pipe*8 + 4) * 8u;

    auto produce = [&](int n) {
        if (n < NCHUNK) {
            if (n >= RINGN)
                mbar_wait(emptyb + (unsigned)(n & 3) * 8u, (unsigned)(((n >> 2) - 1) & 1));
            if (lane == 0) {
                int st = rA + n * CHROWS;
                if (st > H - CHROWS) st = H - CHROWS;   // only p1Last chunk16
                mbar_expect(fullb + (unsigned)(n & 3) * 8u, CHB);
                bulk_cp(psm + (unsigned)(n & 3) * CHB,
                        base + (size_t)st * W, CHB,
                        fullb + (unsigned)(n & 3) * 8u);
            }
            __syncwarp();
        }
    };

    if (cw == 0) {
        if (lane == 0)
            asm volatile("fence.proxy.async.shared::cta;" ::: "memory");
        __syncwarp();
        produce(0);
        produce(1);
        produce(2);
    }

    const int c0 = cw * 256;
    const bool rightEdge = (cw == 1);
    const int cL = (c0 == 0) ? 0 : c0 - 1;
    const int cR = c0 + 256;                  // only read when !rightEdge
    const int tcol = c0 + lane * CPT;

    const char* pipebase = sdata + pipe * PIPEB;

    auto read_slot = [&](const char* p, float x[CPT], float& xL, float& xR) {
        float4 a = *reinterpret_cast<const float4*>(p + tcol * 4);
        float4 b = *reinterpret_cast<const float4*>(p + tcol * 4 + 16);
        x[0]=a.x; x[1]=a.y; x[2]=a.z; x[3]=a.w;
        x[4]=b.x; x[5]=b.y; x[6]=b.z; x[7]=b.w;
        xL = (lane == 0)                ? *reinterpret_cast<const float*>(p + cL * 4) : 0.0f;
        xR = (!rightEdge && lane == 31) ? *reinterpret_cast<const float*>(p + cR * 4) : 0.0f;
    };

    Carry C;
    float acc = 0.0f;

    // ── chunk 0 (peeled): init carry (+1 body step if dupInit) ──
    mbar_wait(fullb, 0u);
    {
        float xa[CPT], xb[CPT], xLa, xRa, xLb, xRb;
        read_slot(pipebase, xa, xLa, xRa);                    // j=0
        if (!dupInit) {
            read_slot(pipebase + 2048, xb, xLb, xRb);         // j=1
        } else {
#pragma unroll
            for (int i = 0; i < CPT; i++) xb[i] = xa[i];
            xLb = xLa; xRb = xRa;
        }
        float vm[CPT];
#pragma unroll
        for (int i = 0; i < CPT; i++) vm[i] = fminf(xa[i], xb[i]);
        float vmL = fminf(xLa, xLb);
        float vmR = fminf(xRa, xRb);
        float left = __shfl_up_sync(FULLM, vm[CPT-1], 1);
        if (lane == 0) left = vmL;
        C.erp[0] = fminf(left, vm[0]);
#pragma unroll
        for (int i = 1; i < CPT; i++) C.erp[i] = fminf(vm[i-1], vm[i]);
        C.erpR = fminf(vm[CPT-1], vmR);
#pragma unroll
        for (int i = 0; i < CPT; i++) C.xp[i] = xb[i];
        C.xLp = xLb; C.xRp = xRb;

        if (dupInit) {                                        // body j=1
            float xc[CPT], xLc, xRc;
            read_slot(pipebase + 2048, xc, xLc, xRc);
            step_compute(xc, xLc, xRc, lane, rightEdge, C, acc);
        }
    }
    __syncwarp();
    if (lane == 0) mbar_arrive(emptyb);
    if (cw == 0) produce(3);

    // ── chunks 1..15: always fully valid, 2 steps each (j = 2cc, 2cc+1) ──
#pragma unroll 1
    for (int cc = 1; cc <= 15; cc++) {
        mbar_wait(fullb + (unsigned)(cc & 3) * 8u, (unsigned)((cc >> 2) & 1));
        const char* cb = pipebase + (cc & 3) * CHB;
        {
            float xc[CPT], xLc, xRc;
            read_slot(cb, xc, xLc, xRc);
            step_compute(xc, xLc, xRc, lane, rightEdge, C, acc);
            read_slot(cb + 2048, xc, xLc, xRc);
            step_compute(xc, xLc, xRc, lane, rightEdge, C, acc);
        }
        __syncwarp();
        if (lane == 0) mbar_arrive(emptyb + (unsigned)(cc & 3) * 8u);
        if (cw == 0) produce(cc + 3);
    }

    // ── chunk 16 (peeled): j=32 (+ j=33 in the fully-normal case) ──
    {
        mbar_wait(fullb + 0u, 0u);                            // stage 16&3=0, phase (16>>2)&1=0
        const char* cb = pipebase;                            // stage 0
        float xc[CPT], xLc, xRc;
        if (!p1Last) {
            read_slot(cb, xc, xLc, xRc);                      // j=32
            step_compute(xc, xLc, xRc, lane, rightEdge, C, acc);
            if (!dupInit) {
                read_slot(cb + 2048, xc, xLc, xRc);           // j=33
                step_compute(xc, xLc, xRc, lane, rightEdge, C, acc);
            }
        } else {
            // clamped chunk: slot1 holds row 511 (the j=32 data)
            read_slot(cb + 2048, xc, xLc, xRc);
            step_compute(xc, xLc, xRc, lane, rightEdge, C, acc);
            final_emit(lane, rightEdge, C, acc);              // emit row 511
        }
    }

    // ── deterministic reduction ──
#pragma unroll
    for (int off = 16; off; off >>= 1)
        acc += __shfl_xor_sync(FULLM, acc, off);

    __shared__ float s[WPB];
    __shared__ bool is_last;
    if (lane == 0) s[wid] = acc;
    __syncthreads();
    if (threadIdx.x == 0) {
        float tsum = 0.0f;
#pragma unroll
        for (int i = 0; i < WPB; i++) tsum += s[i];
        g_partials[blockIdx.x] = tsum;
        __threadfence();
        unsigned v = atomicAdd(&g_count, 1u);
        is_last = (v == GRID - 1);
    }
    __syncthreads();

    if (is_last) {
        __shared__ float r[BLOCK];
        float v = 0.0f;
#pragma unroll
        for (int k = 0; k < GRID / BLOCK; k++)
            v += g_partials[threadIdx.x + k * BLOCK];
        r[threadIdx.x] = v;
        __syncthreads();
#pragma unroll
        for (int off = BLOCK / 2; off > 0; off >>= 1) {
            if (threadIdx.x < off) r[threadIdx.x] += r[threadIdx.x + off];
            __syncthreads();
        }
        if (threadIdx.x == 0) {
            out[0] = r[0] * (1.0f / NELEM);
            g_count = 0;
        }
    }
}

extern "C" void kernel_launch(void* const* d_in, const int* in_sizes, int n_in,
                              void* d_out, int out_size) {
    const float* labels = (const float*)d_in[0];
    float* out = (float*)d_out;
    opening_loss_kernel<<<GRID, BLOCK>>>(labels, out);
}

// round 17
// speedup vs baseline: 1.2973x; 1.2973x over previous
#include <cuda_runtime.h>
#include <cuda_bf16.h>
#include <cstdint>

#define W 512
#define H 512
#define IMGS 128
#define STRIPB 64                      // rows per CTA
#define STRIPS (H / STRIPB)            // 8
#define BLOCK 128
#define WPB 4
#define GRID (IMGS * STRIPS)           // 1024
#define CPT 8
#define NELEM 33554432.0f
#define FULLM 0xffffffffu

#define CHROWS 2
#define CHB (CHROWS * W * 4)           // 4096
#define RINGN 3
#define PIPEB (RINGN * CHB)            // 12288
#define NCHUNK 17                      // chunks per pipe (34 logical rows)

__device__ float g_partials[GRID];
__device__ unsigned int g_count;

__device__ __forceinline__ void mbar_init(unsigned bar, unsigned cnt) {
    asm volatile("mbarrier.init.shared.b64 [%0], %1;" :: "r"(bar), "r"(cnt) : "memory");
}
__device__ __forceinline__ void mbar_wait(unsigned bar, unsigned parity) {
    asm volatile(
        "{\n\t.reg .pred P;\n\t"
        "WL_%=:\n\t"
        "mbarrier.try_wait.parity.acquire.cta.shared::cta.b64 P, [%0], %1, 0x989680;\n\t"
        "@P bra.uni WD_%=;\n\t"
        "bra.uni WL_%=;\n\t"
        "WD_%=:\n\t}"
        :: "r"(bar), "r"(parity) : "memory");
}
__device__ __forceinline__ void mbar_arrive(unsigned bar) {
    asm volatile("mbarrier.arrive.shared.b64 _, [%0];" :: "r"(bar) : "memory");
}
__device__ __forceinline__ void mbar_expect(unsigned bar, unsigned bytes) {
    asm volatile("mbarrier.arrive.expect_tx.shared.b64 _, [%0], %1;"
                 :: "r"(bar), "r"(bytes) : "memory");
}
__device__ __forceinline__ void bulk_cp(unsigned dst, const float* src, unsigned bytes,
                                        unsigned bar) {
    asm volatile("cp.async.bulk.shared::cta.global.mbarrier::complete_tx::bytes "
                 "[%0], [%1], %2, [%3];"
                 :: "r"(dst), "l"(src), "r"(bytes), "r"(bar) : "memory");
}

struct Carry {
    float xp[CPT];
    float erp[CPT];
    float xLp, xRp;
    float erpR;
};

__device__ __forceinline__ void step_compute(const float xc[CPT], float xLc, float xRc,
                                             int lane, bool rightEdge,
                                             Carry& C, float& acc) {
    float vm[CPT];
#pragma unroll
    for (int i = 0; i < CPT; i++) vm[i] = fminf(C.xp[i], xc[i]);
    float vmL = fminf(C.xLp, xLc);
    float vmR = fminf(C.xRp, xRc);

    float left = __shfl_up_sync(FULLM, vm[CPT-1], 1);
    if (lane == 0) left = vmL;
    float ern[CPT];
    ern[0] = fminf(left, vm[0]);
#pragma unroll
    for (int i = 1; i < CPT; i++) ern[i] = fminf(vm[i-1], vm[i]);
    float ernR = fminf(vm[CPT-1], vmR);

    float h[CPT];
#pragma unroll
    for (int i = 0; i < CPT; i++) h[i] = fmaxf(C.erp[i], ern[i]);
    float hR = fmaxf(C.erpR, ernR);

    float hn = __shfl_down_sync(FULLM, h[0], 1);
    if (lane == 31) hn = rightEdge ? h[CPT-1] : hR;
#pragma unroll
    for (int i = 0; i < CPT-1; i++) {
        float di = fmaxf(h[i], h[i+1]);
        float d = C.xp[i] - di;
        acc = fmaf(d, d, acc);
    }
    {
        float di = fmaxf(h[CPT-1], hn);
        float d = C.xp[CPT-1] - di;
        acc = fmaf(d, d, acc);
    }

#pragma unroll
    for (int i = 0; i < CPT; i++) { C.xp[i] = xc[i]; C.erp[i] = ern[i]; }
    C.xLp = xLc; C.xRp = xRc; C.erpR = ernR;
}

__device__ __forceinline__ void final_emit(int lane, bool rightEdge, Carry& C, float& acc) {
    float hn = __shfl_down_sync(FULLM, C.erp[0], 1);
    if (lane == 31) hn = rightEdge ? C.erp[CPT-1] : C.erpR;
#pragma unroll
    for (int i = 0; i < CPT-1; i++) {
        float di = fmaxf(C.erp[i], C.erp[i+1]);
        float d = C.xp[i] - di;
        acc = fmaf(d, d, acc);
    }
    float di = fmaxf(C.erp[CPT-1], hn);
    float d = C.xp[CPT-1] - di;
    acc = fmaf(d, d, acc);
}

__global__ void __launch_bounds__(BLOCK, 7)
opening_loss_kernel(const float* __restrict__ labels, float* __restrict__ out) {
    __shared__ __align__(16) char sdata[2 * PIPEB];            // 24576 B
    __shared__ __align__(8) unsigned long long mbars[16];

    const int lane = threadIdx.x & 31;
    const int wid  = threadIdx.x >> 5;
    const int pipe = wid >> 1;
    const int cw   = wid & 1;

    const int img   = blockIdx.x >> 3;
    const int strip = blockIdx.x & (STRIPS - 1);
    const int r0 = strip * STRIPB;
    const float* base = labels + (size_t)img * (W * H);

    const unsigned mb0 = (unsigned)__cvta_generic_to_shared(mbars);
    // layout: pipe p: full[s] at (p*8+s), empty[s] at (p*8+4+s), s in [0,3)
    if (threadIdx.x == 0) {
#pragma unroll
        for (int p = 0; p < 2; p++) {
#pragma unroll
            for (int s = 0; s < RINGN; s++) {
                mbar_init(mb0 + (p*8+s)*8u, 1u);     // full
                mbar_init(mb0 + (p*8+4+s)*8u, 2u);   // empty (both consumer warps)
            }
        }
    }
    __syncthreads();

    const bool p1 = (pipe == 1);
    const bool lastStrip = (r0 + STRIPB == H);
    const bool dupInit = (!p1 && strip == 0);   // top edge: x[-1]=x[0]
    const bool p1Last  = (p1 && lastStrip);

    const int rA = p1 ? (r0 + 31) : ((r0 > 0) ? r0 - 1 : 0);
    const unsigned psm = (unsigned)__cvta_generic_to_shared(sdata) + pipe * PIPEB;
    const unsigned fullb  = mb0 + (unsigned)(pipe*8)     * 8u;   // + stage*8
    const unsigned emptyb = mb0 + (unsigned)(pipe*8 + 4) * 8u;

    auto produce = [&](int n) {
        if (n < NCHUNK) {
            const int s = n % RINGN;
            if (n >= RINGN)
                mbar_wait(emptyb + (unsigned)s * 8u, (unsigned)((n / RINGN - 1) & 1));
            if (lane == 0) {
                int st = rA + n * CHROWS;
                if (st > H - CHROWS) st = H - CHROWS;   // only p1Last chunk16
                mbar_expect(fullb + (unsigned)s * 8u, CHB);
                bulk_cp(psm + (unsigned)s * CHB,
                        base + (size_t)st * W, CHB,
                        fullb + (unsigned)s * 8u);
            }
            __syncwarp();
        }
    };

    if (cw == 0) {
        if (lane == 0)
            asm volatile("fence.proxy.async.shared::cta;" ::: "memory");
        __syncwarp();
        produce(0);
        produce(1);
        produce(2);
    }

    const int c0 = cw * 256;
    const bool rightEdge = (cw == 1);
    const int cL = (c0 == 0) ? 0 : c0 - 1;
    const int cR = c0 + 256;                  // only read when !rightEdge
    const int tcol = c0 + lane * CPT;

    const char* pipebase = sdata + pipe * PIPEB;

    auto read_slot = [&](const char* p, float x[CPT], float& xL, float& xR) {
        float4 a = *reinterpret_cast<const float4*>(p + tcol * 4);
        float4 b = *reinterpret_cast<const float4*>(p + tcol * 4 + 16);
        x[0]=a.x; x[1]=a.y; x[2]=a.z; x[3]=a.w;
        x[4]=b.x; x[5]=b.y; x[6]=b.z; x[7]=b.w;
        xL = (lane == 0)                ? *reinterpret_cast<const float*>(p + cL * 4) : 0.0f;
        xR = (!rightEdge && lane == 31) ? *reinterpret_cast<const float*>(p + cR * 4) : 0.0f;
    };

    Carry C;
    float acc = 0.0f;

    // ── chunk 0 (peeled): init carry (+1 body step if dupInit) ──
    mbar_wait(fullb, 0u);
    {
        float xa[CPT], xb[CPT], xLa, xRa, xLb, xRb;
        read_slot(pipebase, xa, xLa, xRa);                    // j=0
        if (!dupInit) {
            read_slot(pipebase + 2048, xb, xLb, xRb);         // j=1
        } else {
#pragma unroll
            for (int i = 0; i < CPT; i++) xb[i] = xa[i];
            xLb = xLa; xRb = xRa;
        }
        float vm[CPT];
#pragma unroll
        for (int i = 0; i < CPT; i++) vm[i] = fminf(xa[i], xb[i]);
        float vmL = fminf(xLa, xLb);
        float vmR = fminf(xRa, xRb);
        float left = __shfl_up_sync(FULLM, vm[CPT-1], 1);
        if (lane == 0) left = vmL;
        C.erp[0] = fminf(left, vm[0]);
#pragma unroll
        for (int i = 1; i < CPT; i++) C.erp[i] = fminf(vm[i-1], vm[i]);
        C.erpR = fminf(vm[CPT-1], vmR);
#pragma unroll
        for (int i = 0; i < CPT; i++) C.xp[i] = xb[i];
        C.xLp = xLb; C.xRp = xRb;

        if (dupInit) {                                        // body j=1
            float xc[CPT], xLc, xRc;
            read_slot(pipebase + 2048, xc, xLc, xRc);
            step_compute(xc, xLc, xRc, lane, rightEdge, C, acc);
        }
    }
    __syncwarp();
    if (lane == 0) mbar_arrive(emptyb);
    if (cw == 0) produce(3);

    // ── chunks 1..15: always fully valid, 2 steps each (j = 2cc, 2cc+1) ──
#pragma unroll 1
    for (int cc = 1; cc <= 15; cc++) {
        const int s = cc % RINGN;
        mbar_wait(fullb + (unsigned)s * 8u, (unsigned)((cc / RINGN) & 1));
        const char* cb = pipebase + s * CHB;
        {
            float xc[CPT], xLc, xRc;
            read_slot(cb, xc, xLc, xRc);
            step_compute(xc, xLc, xRc, lane, rightEdge, C, acc);
            read_slot(cb + 2048, xc, xLc, xRc);
            step_compute(xc, xLc, xRc, lane, rightEdge, C, acc);
        }
        __syncwarp();
        if (lane == 0) mbar_arrive(emptyb + (unsigned)s * 8u);
        if (cw == 0) produce(cc + 3);
    }

    // ── chunk 16 (peeled): stage 16%3=1, phase (16/3)&1=1 ──
    {
        mbar_wait(fullb + 8u, 1u);
        const char* cb = pipebase + CHB;                      // stage 1
        float xc[CPT], xLc, xRc;
        if (!p1Last) {
            read_slot(cb, xc, xLc, xRc);                      // j=32
            step_compute(xc, xLc, xRc, lane, rightEdge, C, acc);
            if (!dupInit) {
                read_slot(cb + 2048, xc, xLc, xRc);           // j=33
                step_compute(xc, xLc, xRc, lane, rightEdge, C, acc);
            }
        } else {
            // clamped chunk: slot1 holds row 511 (the j=32 data)
            read_slot(cb + 2048, xc, xLc, xRc);
            step_compute(xc, xLc, xRc, lane, rightEdge, C, acc);
            final_emit(lane, rightEdge, C, acc);              // emit row 511
        }
    }

    // ── deterministic reduction ──
#pragma unroll
    for (int off = 16; off; off >>= 1)
        acc += __shfl_xor_sync(FULLM, acc, off);

    __shared__ float s[WPB];
    __shared__ bool is_last;
    if (lane == 0) s[wid] = acc;
    __syncthreads();
    if (threadIdx.x == 0) {
        float tsum = 0.0f;
#pragma unroll
        for (int i = 0; i < WPB; i++) tsum += s[i];
        g_partials[blockIdx.x] = tsum;
        __threadfence();
        unsigned v = atomicAdd(&g_count, 1u);
        is_last = (v == GRID - 1);
    }
    __syncthreads();

    if (is_last) {
        __shared__ float r[BLOCK];
        float v = 0.0f;
#pragma unroll
        for (int k = 0; k < GRID / BLOCK; k++)
            v += g_partials[threadIdx.x + k * BLOCK];
        r[threadIdx.x] = v;
        __syncthreads();
#pragma unroll
        for (int off = BLOCK / 2; off > 0; off >>= 1) {
            if (threadIdx.x < off) r[threadIdx.x] += r[threadIdx.x + off];
            __syncthreads();
        }
        if (threadIdx.x == 0) {
            out[0] = r[0] * (1.0f / NELEM);
            g_count = 0;
        }
    }
}

extern "C" void kernel_launch(void* const* d_in, const int* in_sizes, int n_in,
                              void* d_out, int out_size) {
    const float* labels = (const float*)d_in[0];
    float* out = (float*)d_out;
    opening_loss_kernel<<<GRID, BLOCK>>>(labels, out);
}